// round 4
// baseline (speedup 1.0000x reference)
#include <cuda_runtime.h>
#include <cuda_bf16.h>

// GPTQLinear: out[16,11008] = x[16,4096] @ W^T + bias, W = (q - z) * s, int4 groups of 128.
// Inputs: x f32[16,4096], qweight i32[11008,2048] (one byte/elem, 2 nibbles),
// scales f32[11008,32], zeros f32[11008,32], bias f32[11008]. Output f32[16,11008].

#define OUTF  11008
#define INF   4096
#define NB    16
#define QI    2048
#define NG    32
#define ROWS_PER_WARP 4
#define WARPS 4
#define THREADS (WARPS * 32)                     // 128
#define ROWS_PER_BLOCK (ROWS_PER_WARP * WARPS)   // 16
#define NBLOCKS (OUTF / ROWS_PER_BLOCK)          // 688
#define CHUNK_COLS 128                           // = one quant group
#define CHUNK_BYTES (CHUNK_COLS / 2)             // 64 ints per row per chunk
#define CHUNK_F4 (CHUNK_BYTES * 8)               // 512 float4 = 8KB x per chunk
#define NCHUNKS (INF / CHUNK_COLS)               // 32
#define TITERS (CHUNK_BYTES / 32)                // 2
#define STAGES 3

// per-stage smem: x 8KB | qw 4KB | sb 128B  -> 12416B, x3 stages = 37248B (<48KB)
#define STG_X    0
#define STG_QW   8192
#define STG_SB   12288
#define STG_SIZE 12416

typedef unsigned long long ull;

__device__ float4 g_xpack[QI * 8];               // xT[4096][16] floats
__device__ float2 g_sB[OUTF * NG];               // {s, -z*s}

#define FMA2(acc, a, b) asm("fma.rn.f32x2 %0, %1, %2, %0;" : "+l"(acc) : "l"(a), "l"(b))
#define ADD2(d, a, b)   asm("add.rn.f32x2 %0, %1, %2;" : "=l"(d) : "l"(a), "l"(b))
#define PACKW(d, w) do { unsigned _wu = __float_as_uint(w); \
    asm("mov.b64 %0, {%1, %1};" : "=l"(d) : "r"(_wu)); } while (0)

__device__ __forceinline__ void cp16(unsigned dst, const void* src) {
    asm volatile("cp.async.cg.shared.global [%0], [%1], 16;" :: "r"(dst), "l"(src));
}
__device__ __forceinline__ void cp8(unsigned dst, const void* src) {
    asm volatile("cp.async.ca.shared.global [%0], [%1], 8;" :: "r"(dst), "l"(src));
}

// Fused prep: blocks [0,64) transpose x; blocks [64,1440) build {s,-z*s}.
__global__ void prep_kernel(const float* __restrict__ x,
                            const float* __restrict__ scales,
                            const float* __restrict__ zeros) {
    if (blockIdx.x < 64) {
        __shared__ float tile[NB][65];
        const int c0 = blockIdx.x * 64;
        const int tid = threadIdx.x;
#pragma unroll
        for (int idx = tid; idx < NB * 64; idx += 256) {
            int r = idx >> 6, col = idx & 63;
            tile[r][col] = x[r * INF + c0 + col];
        }
        __syncthreads();
        float* xo = reinterpret_cast<float*>(g_xpack);
#pragma unroll
        for (int idx = tid; idx < NB * 64; idx += 256) {
            int col = idx >> 4, b = idx & 15;
            xo[(c0 + col) * NB + b] = tile[b][col];
        }
    } else {
        int i = (blockIdx.x - 64) * 256 + threadIdx.x;
        float s = scales[i];
        float z = zeros[i];
        g_sB[i] = make_float2(s, -z * s);
    }
}

__global__ __launch_bounds__(THREADS, 5)
void gptq_main_kernel(const int* __restrict__ qw,
                      const float* __restrict__ bias,
                      float* __restrict__ out) {
    __shared__ char smem_raw[STAGES * STG_SIZE];

    const int tid  = threadIdx.x;
    const int lane = tid & 31;
    const int warp = tid >> 5;
    const int rb0  = blockIdx.x * ROWS_PER_BLOCK;
    const int xr   = lane & 7;

    unsigned smem_u32;
    asm("{ .reg .u64 t; cvta.to.shared.u64 t, %1; cvt.u32.u64 %0, t; }"
        : "=r"(smem_u32) : "l"(smem_raw));

    // ---- async stage of chunk c into stage buffer buf ----
    auto stage = [&](int c, int buf) {
        unsigned sb_base = smem_u32 + buf * STG_SIZE;
        const float4* gx = g_xpack + c * CHUNK_F4;
#pragma unroll
        for (int i = 0; i < CHUNK_F4 / THREADS; ++i) {     // 4
            int idx = tid + i * THREADS;
            cp16(sb_base + STG_X + (unsigned)((idx ^ ((idx >> 3) & 7)) * 16), gx + idx);
        }
#pragma unroll
        for (int p = 0; p < 2; ++p) {
            int li = p * 512 + tid * 4;                    // int index in [0,1024)
            int r = li >> 6, i2 = li & 63;
            cp16(sb_base + STG_QW + (unsigned)(li * 4),
                 qw + (rb0 + r) * QI + c * CHUNK_BYTES + i2);
        }
        if (tid < ROWS_PER_BLOCK)                          // 16 float2, group id == c
            cp8(sb_base + STG_SB + (unsigned)(tid * 8), &g_sB[(rb0 + tid) * NG + c]);
    };

    ull acc[ROWS_PER_WARP][8];
#pragma unroll
    for (int r = 0; r < ROWS_PER_WARP; ++r)
#pragma unroll
        for (int k = 0; k < 8; ++k) acc[r][k] = 0ull;

    stage(0, 0);
    asm volatile("cp.async.commit_group;");
    stage(1, 1);
    asm volatile("cp.async.commit_group;");

    int buf = 0;
    for (int c = 0; c < NCHUNKS; ++c) {
        asm volatile("cp.async.wait_group %0;" :: "n"(STAGES - 2));
        __syncthreads();
        // prefetch chunk c+2 into the buffer freed by chunk c-1 (all warps passed sync)
        if (c + 2 < NCHUNKS) {
            int nbuf = buf + 2;
            if (nbuf >= STAGES) nbuf -= STAGES;
            stage(c + 2, nbuf);
        }
        asm volatile("cp.async.commit_group;");

        const char* sbase = smem_raw + buf * STG_SIZE;
        const float4* s_x  = reinterpret_cast<const float4*>(sbase + STG_X);
        const int*    s_qw = reinterpret_cast<const int*>(sbase + STG_QW)
                             + warp * ROWS_PER_WARP * CHUNK_BYTES;
        const float2* s_sb = reinterpret_cast<const float2*>(sbase + STG_SB)
                             + warp * ROWS_PER_WARP;

        // one group per chunk: hoist dequant constants
        float2 sB[ROWS_PER_WARP];
#pragma unroll
        for (int r = 0; r < ROWS_PER_WARP; ++r) sB[r] = s_sb[r];

#pragma unroll
        for (int t = 0; t < TITERS; ++t) {
            const float4* xbase = s_x + (t * 32 + lane) * 8;

            ull w0p[ROWS_PER_WARP], w1p[ROWS_PER_WARP];
#pragma unroll
            for (int r = 0; r < ROWS_PER_WARP; ++r) {
                const int bv = s_qw[r * CHUNK_BYTES + t * 32 + lane];
                float q0 = __int_as_float(0x4B000000 | (bv & 15)) - 8388608.0f;
                float q1 = __int_as_float(0x4B000000 | ((bv >> 4) & 15)) - 8388608.0f;
                float w0 = fmaf(q0, sB[r].x, sB[r].y);
                float w1 = fmaf(q1, sB[r].x, sB[r].y);
                PACKW(w0p[r], w0);
                PACKW(w1p[r], w1);
            }
#pragma unroll
            for (int q = 0; q < 4; ++q) {
                ulonglong2 v = *reinterpret_cast<const ulonglong2*>(xbase + (q ^ xr));
#pragma unroll
                for (int r = 0; r < ROWS_PER_WARP; ++r) {
                    FMA2(acc[r][2 * q],     v.x, w0p[r]);
                    FMA2(acc[r][2 * q + 1], v.y, w0p[r]);
                }
            }
#pragma unroll
            for (int q = 0; q < 4; ++q) {
                ulonglong2 v = *reinterpret_cast<const ulonglong2*>(xbase + ((q + 4) ^ xr));
#pragma unroll
                for (int r = 0; r < ROWS_PER_WARP; ++r) {
                    FMA2(acc[r][2 * q],     v.x, w1p[r]);
                    FMA2(acc[r][2 * q + 1], v.y, w1p[r]);
                }
            }
        }
        ++buf;
        if (buf >= STAGES) buf = 0;
    }

    // ---- cross-lane reduction: 64-bit shfl butterfly + packed add ----
#pragma unroll
    for (int r = 0; r < ROWS_PER_WARP; ++r)
#pragma unroll
        for (int k = 0; k < 8; ++k) {
            ull v = acc[r][k];
#pragma unroll
            for (int off = 16; off; off >>= 1) {
                ull u = __shfl_xor_sync(0xffffffffu, v, off);
                ADD2(v, v, u);
            }
            acc[r][k] = v;
        }

    // ---- stage output tile [16 batches][16 cols] in smem, coalesced store ----
    __syncthreads();
    float* so = reinterpret_cast<float*>(smem_raw);
#pragma unroll
    for (int r = 0; r < ROWS_PER_WARP; ++r)
#pragma unroll
        for (int k = 0; k < 8; ++k)
            if (lane == r * 8 + k) {
                int col = warp * ROWS_PER_WARP + r;
                so[(2 * k) * ROWS_PER_BLOCK + col] =
                    __uint_as_float((unsigned)(acc[r][k] & 0xffffffffull));
                so[(2 * k + 1) * ROWS_PER_BLOCK + col] =
                    __uint_as_float((unsigned)(acc[r][k] >> 32));
            }
    __syncthreads();

#pragma unroll
    for (int idx = tid; idx < NB * ROWS_PER_BLOCK; idx += THREADS) {
        int b = idx >> 4, col = idx & 15;
        out[b * OUTF + rb0 + col] = so[idx] + bias[rb0 + col];
    }
}

extern "C" void kernel_launch(void* const* d_in, const int* in_sizes, int n_in,
                              void* d_out, int out_size) {
    const float* x      = (const float*)d_in[0];
    const int*   qw     = (const int*)d_in[1];
    const float* scales = (const float*)d_in[2];
    const float* zeros  = (const float*)d_in[3];
    const float* bias   = (const float*)d_in[4];
    float*       out    = (float*)d_out;

    prep_kernel<<<64 + (OUTF * NG) / 256, 256>>>(x, scales, zeros);
    gptq_main_kernel<<<NBLOCKS, THREADS>>>(qw, bias, out);
}

// round 5
// speedup vs baseline: 1.0047x; 1.0047x over previous
#include <cuda_runtime.h>
#include <cuda_bf16.h>

// GPTQLinear: out[16,11008] = x[16,4096] @ W^T + bias, W = (q - z) * s, int4 groups of 128.
// Inputs: x f32[16,4096], qweight i32[11008,2048] (one byte/elem, 2 nibbles),
// scales f32[11008,32], zeros f32[11008,32], bias f32[11008]. Output f32[16,11008].

#define OUTF  11008
#define INF   4096
#define NB    16
#define QI    2048
#define NG    32
#define ROWS_PER_WARP 4
#define WARPS 4
#define THREADS (WARPS * 32)                     // 128
#define ROWS_PER_BLOCK (ROWS_PER_WARP * WARPS)   // 16
#define NBLOCKS (OUTF / ROWS_PER_BLOCK)          // 688
#define CHUNK_COLS 128                           // = one quant group
#define CHUNK_BYTES 64                           // ints per row per chunk
#define NCHUNKS 32
#define TITERS 2
#define STAGES 3
#define XBYTES 8192                              // x chunk: 128 cols x 16 b x 4B
#define QBYTES 4096                              // qw chunk: 16 rows x 64 ints
#define STG_SIZE (XBYTES + QBYTES)               // 12288
#define SBBYTES (ROWS_PER_BLOCK * NG * 8)        // 4096

typedef unsigned long long ull;

__device__ float4 g_xpack[QI * 8];               // xT, PRE-SWIZZLED per 8KB chunk
__device__ float2 g_sB[OUTF * NG];               // {s, -z*s}

#define FMA2(acc, a, b) asm("fma.rn.f32x2 %0, %1, %2, %0;" : "+l"(acc) : "l"(a), "l"(b))
#define ADD2(d, a, b)   asm("add.rn.f32x2 %0, %1, %2;" : "=l"(d) : "l"(a), "l"(b))
#define PACKW(d, w) do { unsigned _wu = __float_as_uint(w); \
    asm("mov.b64 %0, {%1, %1};" : "=l"(d) : "r"(_wu)); } while (0)

__device__ __forceinline__ void cp16(unsigned dst, const void* src) {
    asm volatile("cp.async.cg.shared.global [%0], [%1], 16;" :: "r"(dst), "l"(src));
}
__device__ __forceinline__ void bulk_ld(unsigned dst, const void* src, unsigned bytes,
                                        unsigned bar) {
    asm volatile("cp.async.bulk.shared::cta.global.mbarrier::complete_tx::bytes "
                 "[%0], [%1], %2, [%3];" :: "r"(dst), "l"(src), "r"(bytes), "r"(bar)
                 : "memory");
}
__device__ __forceinline__ void mbar_init(unsigned bar) {
    asm volatile("mbarrier.init.shared.b64 [%0], 1;" :: "r"(bar) : "memory");
}
__device__ __forceinline__ void mbar_expect(unsigned bar, unsigned bytes) {
    asm volatile("mbarrier.arrive.expect_tx.shared.b64 _, [%0], %1;"
                 :: "r"(bar), "r"(bytes) : "memory");
}
__device__ __forceinline__ void mbar_wait(unsigned bar, unsigned par) {
    asm volatile("{\n\t.reg .pred P;\nLW%=:\n\t"
                 "mbarrier.try_wait.parity.shared.b64 P, [%0], %1;\n\t"
                 "@!P bra LW%=;\n\t}" :: "r"(bar), "r"(par) : "memory");
}

// Fused prep: blocks [0,64) transpose x into PRE-SWIZZLED g_xpack; rest build {s,-z*s}.
__global__ void prep_kernel(const float* __restrict__ x,
                            const float* __restrict__ scales,
                            const float* __restrict__ zeros) {
    if (blockIdx.x < 64) {
        __shared__ float tile[NB][65];
        const int c0 = blockIdx.x * 64;
        const int tid = threadIdx.x;
#pragma unroll
        for (int idx = tid; idx < NB * 64; idx += 256) {
            int r = idx >> 6, col = idx & 63;
            tile[r][col] = x[r * INF + c0 + col];
        }
        __syncthreads();
        float* xo = reinterpret_cast<float*>(g_xpack);
#pragma unroll
        for (int idx = tid; idx < NB * 64; idx += 256) {
            int col = idx >> 4, b = idx & 15;
            int j  = (c0 + col) * 4 + (b >> 2);          // float4 index
            int jl = j & 511;
            int dj = (j & ~511) | (jl ^ ((jl >> 3) & 7)); // bake chunk-local swizzle
            xo[dj * 4 + (b & 3)] = tile[b][col];
        }
    } else {
        int i = (blockIdx.x - 64) * 256 + threadIdx.x;
        float s = scales[i];
        float z = zeros[i];
        g_sB[i] = make_float2(s, -z * s);
    }
}

__global__ __launch_bounds__(THREADS, 5)
void gptq_main_kernel(const int* __restrict__ qw,
                      const float* __restrict__ bias,
                      float* __restrict__ out) {
    __shared__ __align__(128) char smem_raw[STAGES * STG_SIZE + SBBYTES];
    __shared__ __align__(8) ull bars[STAGES];

    const int tid  = threadIdx.x;
    const int lane = tid & 31;
    const int warp = tid >> 5;
    const int rb0  = blockIdx.x * ROWS_PER_BLOCK;
    const int xr   = lane & 7;

    unsigned smem_u32, bar0;
    asm("{ .reg .u64 t; cvta.to.shared.u64 t, %1; cvt.u32.u64 %0, t; }"
        : "=r"(smem_u32) : "l"(smem_raw));
    asm("{ .reg .u64 t; cvta.to.shared.u64 t, %1; cvt.u32.u64 %0, t; }"
        : "=r"(bar0) : "l"(bars));

    if (tid == 0) {
#pragma unroll
        for (int s = 0; s < STAGES; ++s) mbar_init(bar0 + s * 8);
    }
    __syncthreads();

    // running gmem pointers (advanced after every stage)
    const char* gxp   = reinterpret_cast<const char*>(g_xpack);
    const int*  qsrc0 = qw + (rb0 +     (tid >> 4)) * QI + ((tid * 4) & 63);
    const int*  qsrc1 = qw + (rb0 + 8 + (tid >> 4)) * QI + ((tid * 4) & 63);
    const unsigned qd0 = tid * 16;            // smem byte offsets within qw region
    const unsigned qd1 = 2048 + tid * 16;

    // ---- prologue: stage chunks 0,1 + scale table ----
    if (tid == 0) {
        mbar_expect(bar0, XBYTES + SBBYTES);
        bulk_ld(smem_u32 + 0 * STG_SIZE, gxp, XBYTES, bar0);
        bulk_ld(smem_u32 + STAGES * STG_SIZE, g_sB + rb0 * NG, SBBYTES, bar0);
        mbar_expect(bar0 + 8, XBYTES);
        bulk_ld(smem_u32 + 1 * STG_SIZE, gxp + XBYTES, XBYTES, bar0 + 8);
    }
    {
        unsigned sq = smem_u32 + XBYTES;
        cp16(sq + qd0, qsrc0); cp16(sq + qd1, qsrc1);
        asm volatile("cp.async.commit_group;");
        qsrc0 += CHUNK_BYTES; qsrc1 += CHUNK_BYTES;
        sq += STG_SIZE;
        cp16(sq + qd0, qsrc0); cp16(sq + qd1, qsrc1);
        asm volatile("cp.async.commit_group;");
        qsrc0 += CHUNK_BYTES; qsrc1 += CHUNK_BYTES;
    }
    gxp += 2 * XBYTES;

    const float2* s_sb = reinterpret_cast<const float2*>(
        smem_raw + STAGES * STG_SIZE) + (warp * ROWS_PER_WARP) * NG;

    ull acc[ROWS_PER_WARP][8];
#pragma unroll
    for (int r = 0; r < ROWS_PER_WARP; ++r)
#pragma unroll
        for (int k = 0; k < 8; ++k) acc[r][k] = 0ull;

    int buf = 0, par = 0;
    for (int c = 0; c < NCHUNKS; ++c) {
        mbar_wait(bar0 + buf * 8, par);                  // x chunk c ready
        asm volatile("cp.async.wait_group 1;");          // qw chunk c ready
        __syncthreads();                                 // all done with chunk c-1

        int nbuf = buf + 2; if (nbuf >= STAGES) nbuf -= STAGES;
        if (c + 2 < NCHUNKS) {
            if (tid == 0) {
                mbar_expect(bar0 + nbuf * 8, XBYTES);
                bulk_ld(smem_u32 + nbuf * STG_SIZE, gxp, XBYTES, bar0 + nbuf * 8);
            }
            unsigned sq = smem_u32 + nbuf * STG_SIZE + XBYTES;
            cp16(sq + qd0, qsrc0); cp16(sq + qd1, qsrc1);
            qsrc0 += CHUNK_BYTES; qsrc1 += CHUNK_BYTES;
            gxp += XBYTES;
        }
        asm volatile("cp.async.commit_group;");

        const char* sbase = smem_raw + buf * STG_SIZE;
        const float4* s_x  = reinterpret_cast<const float4*>(sbase);
        const int*    s_qw = reinterpret_cast<const int*>(sbase + XBYTES)
                             + warp * ROWS_PER_WARP * CHUNK_BYTES;

        float2 sB[ROWS_PER_WARP];                        // one group per chunk
#pragma unroll
        for (int r = 0; r < ROWS_PER_WARP; ++r) sB[r] = s_sb[r * NG + c];

#pragma unroll
        for (int t = 0; t < TITERS; ++t) {
            const float4* xbase = s_x + (t * 32 + lane) * 8;

            ull w0p[ROWS_PER_WARP], w1p[ROWS_PER_WARP];
#pragma unroll
            for (int r = 0; r < ROWS_PER_WARP; ++r) {
                const int bv = s_qw[r * CHUNK_BYTES + t * 32 + lane];
                float q0 = __int_as_float(0x4B000000 | (bv & 15)) - 8388608.0f;
                float q1 = __int_as_float(0x4B000000 | ((bv >> 4) & 15)) - 8388608.0f;
                float w0 = fmaf(q0, sB[r].x, sB[r].y);
                float w1 = fmaf(q1, sB[r].x, sB[r].y);
                PACKW(w0p[r], w0);
                PACKW(w1p[r], w1);
            }
#pragma unroll
            for (int q = 0; q < 4; ++q) {
                ulonglong2 v = *reinterpret_cast<const ulonglong2*>(xbase + (q ^ xr));
#pragma unroll
                for (int r = 0; r < ROWS_PER_WARP; ++r) {
                    FMA2(acc[r][2 * q],     v.x, w0p[r]);
                    FMA2(acc[r][2 * q + 1], v.y, w0p[r]);
                }
            }
#pragma unroll
            for (int q = 0; q < 4; ++q) {
                ulonglong2 v = *reinterpret_cast<const ulonglong2*>(xbase + ((q + 4) ^ xr));
#pragma unroll
                for (int r = 0; r < ROWS_PER_WARP; ++r) {
                    FMA2(acc[r][2 * q],     v.x, w1p[r]);
                    FMA2(acc[r][2 * q + 1], v.y, w1p[r]);
                }
            }
        }
        ++buf;
        if (buf >= STAGES) { buf = 0; par ^= 1; }
    }

    // ---- cross-lane reduction: 64-bit shfl butterfly + packed add ----
#pragma unroll
    for (int r = 0; r < ROWS_PER_WARP; ++r)
#pragma unroll
        for (int k = 0; k < 8; ++k) {
            ull v = acc[r][k];
#pragma unroll
            for (int off = 16; off; off >>= 1) {
                ull u = __shfl_xor_sync(0xffffffffu, v, off);
                ADD2(v, v, u);
            }
            acc[r][k] = v;
        }

    // ---- stage output tile [16 batches][16 cols] in smem, coalesced store ----
    asm volatile("cp.async.wait_group 0;");
    __syncthreads();
    float* so = reinterpret_cast<float*>(smem_raw);
#pragma unroll
    for (int r = 0; r < ROWS_PER_WARP; ++r)
#pragma unroll
        for (int k = 0; k < 8; ++k)
            if (lane == r * 8 + k) {
                int col = warp * ROWS_PER_WARP + r;
                so[(2 * k) * ROWS_PER_BLOCK + col] =
                    __uint_as_float((unsigned)(acc[r][k] & 0xffffffffull));
                so[(2 * k + 1) * ROWS_PER_BLOCK + col] =
                    __uint_as_float((unsigned)(acc[r][k] >> 32));
            }
    __syncthreads();

#pragma unroll
    for (int idx = tid; idx < NB * ROWS_PER_BLOCK; idx += THREADS) {
        int b = idx >> 4, col = idx & 15;
        out[b * OUTF + rb0 + col] = so[idx] + bias[rb0 + col];
    }
}

extern "C" void kernel_launch(void* const* d_in, const int* in_sizes, int n_in,
                              void* d_out, int out_size) {
    const float* x      = (const float*)d_in[0];
    const int*   qw     = (const int*)d_in[1];
    const float* scales = (const float*)d_in[2];
    const float* zeros  = (const float*)d_in[3];
    const float* bias   = (const float*)d_in[4];
    float*       out    = (float*)d_out;

    prep_kernel<<<64 + (OUTF * NG) / 256, 256>>>(x, scales, zeros);
    gptq_main_kernel<<<NBLOCKS, THREADS>>>(qw, bias, out);
}

// round 6
// speedup vs baseline: 1.0080x; 1.0033x over previous
#include <cuda_runtime.h>
#include <cuda_bf16.h>

// GPTQLinear: out[16,11008] = x[16,4096] @ W^T + bias, W = (q - z) * s, int4 groups of 128.
// Inputs: x f32[16,4096], qweight i32[11008,2048] (one byte/elem, 2 nibbles),
// scales f32[11008,32], zeros f32[11008,32], bias f32[11008]. Output f32[16,11008].

#define OUTF  11008
#define INF   4096
#define NB    16
#define QI    2048
#define NG    32
#define ROWS_PER_WARP 4
#define WARPS 4
#define THREADS (WARPS * 32)                     // 128
#define ROWS_PER_BLOCK (ROWS_PER_WARP * WARPS)   // 16
#define NBLOCKS (OUTF / ROWS_PER_BLOCK)          // 688
#define CHUNK_COLS 128                           // = one quant group
#define CHUNK_BYTES 64                           // ints per row per chunk
#define NCHUNKS 32
#define TITERS 2
#define STAGES 3
#define XBYTES 8192                              // x chunk: 128 cols x 16 b x 4B
#define QBYTES 4096                              // qw chunk: 16 rows x 64 ints
#define STG_SIZE (XBYTES + QBYTES)               // 12288
#define SBBYTES (ROWS_PER_BLOCK * NG * 8)        // 4096

typedef unsigned long long ull;

__device__ float4 g_xpack[QI * 8];               // xT, PRE-SWIZZLED per 8KB chunk
__device__ float2 g_sB[OUTF * NG];               // {s, -z*s}

#define FMA2(acc, a, b) asm("fma.rn.f32x2 %0, %1, %2, %0;" : "+l"(acc) : "l"(a), "l"(b))
#define ADD2(d, a, b)   asm("add.rn.f32x2 %0, %1, %2;" : "=l"(d) : "l"(a), "l"(b))
#define PACKW(d, w) do { unsigned _wu = __float_as_uint(w); \
    asm("mov.b64 %0, {%1, %1};" : "=l"(d) : "r"(_wu)); } while (0)

__device__ __forceinline__ void cp16(unsigned dst, const void* src) {
    asm volatile("cp.async.cg.shared.global [%0], [%1], 16;" :: "r"(dst), "l"(src));
}
__device__ __forceinline__ void bulk_ld(unsigned dst, const void* src, unsigned bytes,
                                        unsigned bar) {
    asm volatile("cp.async.bulk.shared::cta.global.mbarrier::complete_tx::bytes "
                 "[%0], [%1], %2, [%3];" :: "r"(dst), "l"(src), "r"(bytes), "r"(bar)
                 : "memory");
}
__device__ __forceinline__ void mbar_init(unsigned bar) {
    asm volatile("mbarrier.init.shared.b64 [%0], 1;" :: "r"(bar) : "memory");
}
__device__ __forceinline__ void mbar_expect(unsigned bar, unsigned bytes) {
    asm volatile("mbarrier.arrive.expect_tx.shared.b64 _, [%0], %1;"
                 :: "r"(bar), "r"(bytes) : "memory");
}
__device__ __forceinline__ void mbar_wait(unsigned bar, unsigned par) {
    asm volatile("{\n\t.reg .pred P;\nLW%=:\n\t"
                 "mbarrier.try_wait.parity.shared.b64 P, [%0], %1;\n\t"
                 "@!P bra LW%=;\n\t}" :: "r"(bar), "r"(par) : "memory");
}

// Fused prep: blocks [0,64) transpose x into PRE-SWIZZLED g_xpack; rest build {s,-z*s}.
__global__ void prep_kernel(const float* __restrict__ x,
                            const float* __restrict__ scales,
                            const float* __restrict__ zeros) {
    if (blockIdx.x < 64) {
        __shared__ float tile[NB][65];
        const int c0 = blockIdx.x * 64;
        const int tid = threadIdx.x;
#pragma unroll
        for (int idx = tid; idx < NB * 64; idx += 256) {
            int r = idx >> 6, col = idx & 63;
            tile[r][col] = x[r * INF + c0 + col];
        }
        __syncthreads();
        float* xo = reinterpret_cast<float*>(g_xpack);
#pragma unroll
        for (int idx = tid; idx < NB * 64; idx += 256) {
            int col = idx >> 4, b = idx & 15;
            int j  = (c0 + col) * 4 + (b >> 2);          // float4 index
            int jl = j & 511;
            int dj = (j & ~511) | (jl ^ ((jl >> 3) & 7)); // bake chunk-local swizzle
            xo[dj * 4 + (b & 3)] = tile[b][col];
        }
    } else {
        int i = (blockIdx.x - 64) * 256 + threadIdx.x;
        float s = scales[i];
        float z = zeros[i];
        g_sB[i] = make_float2(s, -z * s);
    }
}

__global__ __launch_bounds__(THREADS, 5)
void gptq_main_kernel(const int* __restrict__ qw,
                      const float* __restrict__ bias,
                      float* __restrict__ out) {
    __shared__ __align__(128) char smem_raw[STAGES * STG_SIZE + SBBYTES];
    __shared__ __align__(8) ull bars[STAGES];

    const int tid  = threadIdx.x;
    const int lane = tid & 31;
    const int warp = tid >> 5;
    const int rb0  = blockIdx.x * ROWS_PER_BLOCK;
    const int xr   = lane & 7;

    unsigned smem_u32, bar0;
    asm("{ .reg .u64 t; cvta.to.shared.u64 t, %1; cvt.u32.u64 %0, t; }"
        : "=r"(smem_u32) : "l"(smem_raw));
    asm("{ .reg .u64 t; cvta.to.shared.u64 t, %1; cvt.u32.u64 %0, t; }"
        : "=r"(bar0) : "l"(bars));

    if (tid == 0) {
#pragma unroll
        for (int s = 0; s < STAGES; ++s) mbar_init(bar0 + s * 8);
    }
    __syncthreads();

    // running gmem pointers (advanced after every stage)
    const char* gxp   = reinterpret_cast<const char*>(g_xpack);
    const int*  qsrc0 = qw + (rb0 +     (tid >> 4)) * QI + ((tid * 4) & 63);
    const int*  qsrc1 = qw + (rb0 + 8 + (tid >> 4)) * QI + ((tid * 4) & 63);
    const unsigned qd0 = tid * 16;            // smem byte offsets within qw region
    const unsigned qd1 = 2048 + tid * 16;

    // ---- prologue: stage chunks 0,1 + scale table ----
    if (tid == 0) {
        mbar_expect(bar0, XBYTES + SBBYTES);
        bulk_ld(smem_u32 + 0 * STG_SIZE, gxp, XBYTES, bar0);
        bulk_ld(smem_u32 + STAGES * STG_SIZE, g_sB + rb0 * NG, SBBYTES, bar0);
        mbar_expect(bar0 + 8, XBYTES);
        bulk_ld(smem_u32 + 1 * STG_SIZE, gxp + XBYTES, XBYTES, bar0 + 8);
    }
    {
        unsigned sq = smem_u32 + XBYTES;
        cp16(sq + qd0, qsrc0); cp16(sq + qd1, qsrc1);
        asm volatile("cp.async.commit_group;");
        qsrc0 += CHUNK_BYTES; qsrc1 += CHUNK_BYTES;
        sq += STG_SIZE;
        cp16(sq + qd0, qsrc0); cp16(sq + qd1, qsrc1);
        asm volatile("cp.async.commit_group;");
        qsrc0 += CHUNK_BYTES; qsrc1 += CHUNK_BYTES;
    }
    gxp += 2 * XBYTES;

    const float2* s_sb = reinterpret_cast<const float2*>(
        smem_raw + STAGES * STG_SIZE) + (warp * ROWS_PER_WARP) * NG;

    ull acc[ROWS_PER_WARP][8];
#pragma unroll
    for (int r = 0; r < ROWS_PER_WARP; ++r)
#pragma unroll
        for (int k = 0; k < 8; ++k) acc[r][k] = 0ull;

    int buf = 0, par = 0;
    for (int c = 0; c < NCHUNKS; ++c) {
        mbar_wait(bar0 + buf * 8, par);                  // x chunk c ready
        asm volatile("cp.async.wait_group 1;");          // qw chunk c ready
        __syncthreads();                                 // all done with chunk c-1

        int nbuf = buf + 2; if (nbuf >= STAGES) nbuf -= STAGES;
        if (c + 2 < NCHUNKS) {
            if (tid == 0) {
                mbar_expect(bar0 + nbuf * 8, XBYTES);
                bulk_ld(smem_u32 + nbuf * STG_SIZE, gxp, XBYTES, bar0 + nbuf * 8);
            }
            unsigned sq = smem_u32 + nbuf * STG_SIZE + XBYTES;
            cp16(sq + qd0, qsrc0); cp16(sq + qd1, qsrc1);
            qsrc0 += CHUNK_BYTES; qsrc1 += CHUNK_BYTES;
            gxp += XBYTES;
        }
        asm volatile("cp.async.commit_group;");

        const char* sbase = smem_raw + buf * STG_SIZE;
        const float4* s_x  = reinterpret_cast<const float4*>(sbase);
        const int*    s_qw = reinterpret_cast<const int*>(sbase + XBYTES)
                             + warp * ROWS_PER_WARP * CHUNK_BYTES;

        float2 sB[ROWS_PER_WARP];                        // one group per chunk
#pragma unroll
        for (int r = 0; r < ROWS_PER_WARP; ++r) sB[r] = s_sb[r * NG + c];

#pragma unroll
        for (int t = 0; t < TITERS; ++t) {
            const float4* xbase = s_x + (t * 32 + lane) * 8;

            ull w0p[ROWS_PER_WARP], w1p[ROWS_PER_WARP];
#pragma unroll
            for (int r = 0; r < ROWS_PER_WARP; ++r) {
                const int bv = s_qw[r * CHUNK_BYTES + t * 32 + lane];
                float q0 = __int_as_float(0x4B000000 | (bv & 15)) - 8388608.0f;
                float q1 = __int_as_float(0x4B000000 | ((bv >> 4) & 15)) - 8388608.0f;
                float w0 = fmaf(q0, sB[r].x, sB[r].y);
                float w1 = fmaf(q1, sB[r].x, sB[r].y);
                PACKW(w0p[r], w0);
                PACKW(w1p[r], w1);
            }
#pragma unroll
            for (int q = 0; q < 4; ++q) {
                ulonglong2 v = *reinterpret_cast<const ulonglong2*>(xbase + (q ^ xr));
#pragma unroll
                for (int r = 0; r < ROWS_PER_WARP; ++r) {
                    FMA2(acc[r][2 * q],     v.x, w0p[r]);
                    FMA2(acc[r][2 * q + 1], v.y, w0p[r]);
                }
            }
#pragma unroll
            for (int q = 0; q < 4; ++q) {
                ulonglong2 v = *reinterpret_cast<const ulonglong2*>(xbase + ((q + 4) ^ xr));
#pragma unroll
                for (int r = 0; r < ROWS_PER_WARP; ++r) {
                    FMA2(acc[r][2 * q],     v.x, w1p[r]);
                    FMA2(acc[r][2 * q + 1], v.y, w1p[r]);
                }
            }
        }
        ++buf;
        if (buf >= STAGES) { buf = 0; par ^= 1; }
    }

    // ---- cross-lane reduction: 64-bit shfl butterfly + packed add ----
#pragma unroll
    for (int r = 0; r < ROWS_PER_WARP; ++r)
#pragma unroll
        for (int k = 0; k < 8; ++k) {
            ull v = acc[r][k];
#pragma unroll
            for (int off = 16; off; off >>= 1) {
                ull u = __shfl_xor_sync(0xffffffffu, v, off);
                ADD2(v, v, u);
            }
            acc[r][k] = v;
        }

    // ---- stage output tile [16 batches][16 cols] in smem, coalesced store ----
    asm volatile("cp.async.wait_group 0;");
    __syncthreads();
    float* so = reinterpret_cast<float*>(smem_raw);
#pragma unroll
    for (int r = 0; r < ROWS_PER_WARP; ++r)
#pragma unroll
        for (int k = 0; k < 8; ++k)
            if (lane == r * 8 + k) {
                int col = warp * ROWS_PER_WARP + r;
                so[(2 * k) * ROWS_PER_BLOCK + col] =
                    __uint_as_float((unsigned)(acc[r][k] & 0xffffffffull));
                so[(2 * k + 1) * ROWS_PER_BLOCK + col] =
                    __uint_as_float((unsigned)(acc[r][k] >> 32));
            }
    __syncthreads();

#pragma unroll
    for (int idx = tid; idx < NB * ROWS_PER_BLOCK; idx += THREADS) {
        int b = idx >> 4, col = idx & 15;
        out[b * OUTF + rb0 + col] = so[idx] + bias[rb0 + col];
    }
}

extern "C" void kernel_launch(void* const* d_in, const int* in_sizes, int n_in,
                              void* d_out, int out_size) {
    const float* x      = (const float*)d_in[0];
    const int*   qw     = (const int*)d_in[1];
    const float* scales = (const float*)d_in[2];
    const float* zeros  = (const float*)d_in[3];
    const float* bias   = (const float*)d_in[4];
    float*       out    = (float*)d_out;

    prep_kernel<<<64 + (OUTF * NG) / 256, 256>>>(x, scales, zeros);
    gptq_main_kernel<<<NBLOCKS, THREADS>>>(qw, bias, out);
}